// round 2
// baseline (speedup 1.0000x reference)
#include <cuda_runtime.h>
#include <math.h>

#define Bb 32
#define Hh 32
#define Ll 32768
#define NTOT (Bb*Ll)

// ---------------- scratch (static device allocations, allowed) ----------------
__device__ float2 g_phi[NTOT];        // 8 MB  [b*L+l] -> (phi0, phi1)
__device__ float2 g_psi[NTOT];        // 8 MB  [b*L+l] -> (psi0, psi1)
__device__ float4 g_beta[2*NTOT];     // 32 MB [2*(b*L+l)+{0,1}] -> beta[0..7]

// moment accumulators (zeroed every launch)
__device__ double g_sum1[4], g_ssq1[4];    // raw phi0,phi1,psi0,psi1
__device__ double g_sum2[4], g_ssq2[4];    // t (im)
__device__ double g_sum3[8], g_ssq3[8];    // weight*beta
__device__ double g_sum4[32], g_ssq4[32];  // y

// fused BN affines: normalized = a*v + c
__device__ float g_a1[16], g_c1[16];
__device__ float g_a2[4],  g_c2[4];
__device__ float g_a3[8],  g_c3[8];
__device__ float g_a4[32], g_c4[32];

// shared-param layout offsets
#define PA1 0
#define PC1 16
#define PW1 32
#define PB1 96
#define PA2 100
#define PC2 104
#define PW2 108
#define PB2 140
#define PA3 148
#define PC3 156
#define PWO 164
#define PBO 420
#define PA4 452
#define PC4 484
#define PTOT 516

// ---------------- helpers ----------------
template<int NCH>
__device__ __forceinline__ void block_reduce_atomic(const float* acc, double* sums, double* ssqs) {
    __shared__ float red[8][2*NCH];
    int lane = threadIdx.x & 31, warp = threadIdx.x >> 5;
    #pragma unroll
    for (int j = 0; j < 2*NCH; j++) {
        float v = acc[j];
        #pragma unroll
        for (int o = 16; o; o >>= 1) v += __shfl_down_sync(0xffffffffu, v, o);
        if (lane == 0) red[warp][j] = v;
    }
    __syncthreads();
    for (int j = threadIdx.x; j < 2*NCH; j += blockDim.x) {
        float s = 0.f;
        #pragma unroll
        for (int w = 0; w < 8; w++) s += red[w][j];
        if (j < NCH) atomicAdd(&sums[j], (double)s);
        else         atomicAdd(&ssqs[j-NCH], (double)s);
    }
}

__device__ __forceinline__ void compute_t(int b, int l, const float* P, float t[4]) {
    size_t base = (size_t)b * Ll;
    float2 ph = g_phi[base + l];
    float hv[16];
    hv[0] = ph.x; hv[1] = ph.y;
    #pragma unroll
    for (int j = 0; j < 7; j++) {
        int idx = l + j - 3;
        float2 p = (idx >= 0 && idx < Ll) ? g_psi[base + idx] : make_float2(0.f, 0.f);
        hv[2+j] = p.x; hv[9+j] = p.y;
    }
    float t0 = P[PB1+0], t1 = P[PB1+1], t2 = P[PB1+2], t3 = P[PB1+3];
    #pragma unroll
    for (int ch = 0; ch < 16; ch++) {
        float v = fmaxf(fmaf(P[PA1+ch], hv[ch], P[PC1+ch]), 0.f);
        t0 = fmaf(P[PW1+0*16+ch], v, t0);
        t1 = fmaf(P[PW1+1*16+ch], v, t1);
        t2 = fmaf(P[PW1+2*16+ch], v, t2);
        t3 = fmaf(P[PW1+3*16+ch], v, t3);
    }
    t[0]=t0; t[1]=t1; t[2]=t2; t[3]=t3;
}

__device__ __forceinline__ void compute_wb(int b, int l, const float* P, float wb[8]) {
    float t[4];
    compute_t(b, l, P, t);
    float u[4];
    #pragma unroll
    for (int i = 0; i < 4; i++) u[i] = fmaxf(fmaf(P[PA2+i], t[i], P[PC2+i]), 0.f);
    float w8[8];
    #pragma unroll
    for (int o = 0; o < 8; o++) {
        float w = P[PB2+o];
        #pragma unroll
        for (int i = 0; i < 4; i++) w = fmaf(P[PW2+o*4+i], u[i], w);
        w8[o] = w;
    }
    size_t idx = (size_t)b * Ll + l;
    float4 b0 = g_beta[2*idx], b1 = g_beta[2*idx+1];
    wb[0]=w8[0]*b0.x; wb[1]=w8[1]*b0.y; wb[2]=w8[2]*b0.z; wb[3]=w8[3]*b0.w;
    wb[4]=w8[4]*b1.x; wb[5]=w8[5]*b1.y; wb[6]=w8[6]*b1.z; wb[7]=w8[7]*b1.w;
}

__device__ __forceinline__ void load_chain(float* P, int level,
        const float* w1, const float* b1, const float* w2, const float* b2,
        const float* wo, const float* bo) {
    int t = threadIdx.x, bd = blockDim.x;
    for (int i = t; i < 16; i += bd) { P[PA1+i] = g_a1[i]; P[PC1+i] = g_c1[i]; }
    for (int i = t; i < 64; i += bd) P[PW1+i] = w1[i];
    for (int i = t; i < 4;  i += bd) P[PB1+i] = b1[i];
    if (level >= 3) {
        for (int i = t; i < 4;  i += bd) { P[PA2+i] = g_a2[i]; P[PC2+i] = g_c2[i]; }
        for (int i = t; i < 32; i += bd) P[PW2+i] = w2[i];
        for (int i = t; i < 8;  i += bd) P[PB2+i] = b2[i];
    }
    if (level >= 4) {
        for (int i = t; i < 8;   i += bd) { P[PA3+i] = g_a3[i]; P[PC3+i] = g_c3[i]; }
        for (int i = t; i < 256; i += bd) P[PWO+i] = wo[i];
        for (int i = t; i < 32;  i += bd) P[PBO+i] = bo[i];
    }
    if (level >= 5) {
        for (int i = t; i < 32; i += bd) { P[PA4+i] = g_a4[i]; P[PC4+i] = g_c4[i]; }
    }
}

// ---------------- kernels ----------------
__global__ void k_zero() {
    int t = threadIdx.x;
    if (t < 4)  { g_sum1[t]=0; g_ssq1[t]=0; g_sum2[t]=0; g_ssq2[t]=0; }
    if (t < 8)  { g_sum3[t]=0; g_ssq3[t]=0; }
    if (t < 32) { g_sum4[t]=0; g_ssq4[t]=0; }
}

// P1: x -> phi, psi, beta ; raw moments of phi/psi
__global__ void __launch_bounds__(256) k_proj(
        const float* __restrict__ x,
        const float* __restrict__ w_phi, const float* __restrict__ b_phi,
        const float* __restrict__ w_psi, const float* __restrict__ b_psi,
        const float* __restrict__ w_beta, const float* __restrict__ b_beta) {
    __shared__ float s_wphi[64], s_wpsi[64], s_wbeta[256], s_b[12];
    for (int i = threadIdx.x; i < 64; i += blockDim.x) { s_wphi[i] = w_phi[i]; s_wpsi[i] = w_psi[i]; }
    for (int i = threadIdx.x; i < 256; i += blockDim.x) s_wbeta[i] = w_beta[i];
    if (threadIdx.x < 2) { s_b[threadIdx.x] = b_phi[threadIdx.x]; s_b[2+threadIdx.x] = b_psi[threadIdx.x]; }
    if (threadIdx.x < 8) s_b[4+threadIdx.x] = b_beta[threadIdx.x];
    __syncthreads();

    int b  = blockIdx.x >> 5;
    int l0 = ((blockIdx.x & 31) << 10) + (threadIdx.x << 2);

    float ph0[4], ph1[4], ps0[4], ps1[4], bt[8][4];
    #pragma unroll
    for (int i = 0; i < 4; i++) {
        ph0[i]=s_b[0]; ph1[i]=s_b[1]; ps0[i]=s_b[2]; ps1[i]=s_b[3];
        #pragma unroll
        for (int o = 0; o < 8; o++) bt[o][i] = s_b[4+o];
    }
    const float* xb = x + (size_t)b * Hh * Ll + l0;
    #pragma unroll 4
    for (int c = 0; c < 32; c++) {
        float4 xv = *reinterpret_cast<const float4*>(xb + (size_t)c * Ll);
        float xa[4] = {xv.x, xv.y, xv.z, xv.w};
        float wp0 = s_wphi[c], wp1 = s_wphi[32+c];
        float wq0 = s_wpsi[c], wq1 = s_wpsi[32+c];
        #pragma unroll
        for (int i = 0; i < 4; i++) {
            ph0[i] = fmaf(wp0, xa[i], ph0[i]); ph1[i] = fmaf(wp1, xa[i], ph1[i]);
            ps0[i] = fmaf(wq0, xa[i], ps0[i]); ps1[i] = fmaf(wq1, xa[i], ps1[i]);
        }
        #pragma unroll
        for (int o = 0; o < 8; o++) {
            float w = s_wbeta[o*32 + c];
            #pragma unroll
            for (int i = 0; i < 4; i++) bt[o][i] = fmaf(w, xa[i], bt[o][i]);
        }
    }
    size_t base = (size_t)b * Ll + l0;
    float acc[8] = {0,0,0,0,0,0,0,0};
    #pragma unroll
    for (int i = 0; i < 4; i++) {
        g_phi[base+i] = make_float2(ph0[i], ph1[i]);
        g_psi[base+i] = make_float2(ps0[i], ps1[i]);
        g_beta[2*(base+i)  ] = make_float4(bt[0][i], bt[1][i], bt[2][i], bt[3][i]);
        g_beta[2*(base+i)+1] = make_float4(bt[4][i], bt[5][i], bt[6][i], bt[7][i]);
        acc[0]+=ph0[i]; acc[4]+=ph0[i]*ph0[i];
        acc[1]+=ph1[i]; acc[5]+=ph1[i]*ph1[i];
        acc[2]+=ps0[i]; acc[6]+=ps0[i]*ps0[i];
        acc[3]+=ps1[i]; acc[7]+=ps1[i]*ps1[i];
    }
    block_reduce_atomic<4>(acc, g_sum1, g_ssq1);
}

// BN1 finalize: shifted-psi channel stats from totals + edge corrections
__global__ void k_fin1(const float* __restrict__ gcat, const float* __restrict__ becat) {
    __shared__ float edge[32][6][2];
    int tid = threadIdx.x;
    if (tid < 192) {
        int b = tid / 6, e = tid % 6;
        int idx = (e < 3) ? e : (Ll - 6 + e);
        float2 p = g_psi[(size_t)b * Ll + idx];
        edge[b][e][0] = p.x; edge[b][e][1] = p.y;
    }
    __syncthreads();
    if (tid < 16) {
        int ch = tid;
        double sum, ssq;
        if (ch < 2) { sum = g_sum1[ch]; ssq = g_ssq1[ch]; }
        else {
            int c = (ch - 2) / 7, j = (ch - 2) % 7, s = j - 3;
            sum = g_sum1[2+c]; ssq = g_ssq1[2+c];
            if (s > 0) {
                for (int b = 0; b < 32; b++)
                    for (int i = 0; i < s; i++) {
                        double v = edge[b][i][c]; sum -= v; ssq -= v*v;
                    }
            } else if (s < 0) {
                for (int b = 0; b < 32; b++)
                    for (int i = 0; i < -s; i++) {
                        double v = edge[b][6+s+i][c]; sum -= v; ssq -= v*v;
                    }
            }
        }
        double mean = sum / (double)NTOT;
        double var  = ssq / (double)NTOT - mean * mean;
        float a = gcat[ch] * (float)(1.0 / sqrt(var + 1e-5));
        g_a1[ch] = a;
        g_c1[ch] = becat[ch] - (float)mean * a;
    }
}

// generic BN finalize for stages 2/3/4
__global__ void k_fin(int which, const float* __restrict__ g, const float* __restrict__ be) {
    const double *sum, *ssq; float *a, *c; int n;
    if (which == 2)      { sum=g_sum2; ssq=g_ssq2; a=g_a2; c=g_c2; n=4; }
    else if (which == 3) { sum=g_sum3; ssq=g_ssq3; a=g_a3; c=g_c3; n=8; }
    else                 { sum=g_sum4; ssq=g_ssq4; a=g_a4; c=g_c4; n=32; }
    int j = threadIdx.x;
    if (j < n) {
        double mean = sum[j] / (double)NTOT;
        double var  = ssq[j] / (double)NTOT - mean * mean;
        float av = g[j] * (float)(1.0 / sqrt(var + 1e-5));
        a[j] = av;
        c[j] = be[j] - (float)mean * av;
    }
}

// P2: moments of t (for BN2)
__global__ void __launch_bounds__(256) k_stats2(const float* __restrict__ w1, const float* __restrict__ b1) {
    __shared__ float P[PA2];
    load_chain(P, 2, w1, b1, 0, 0, 0, 0);
    __syncthreads();
    int b  = blockIdx.x >> 5;
    int l0 = ((blockIdx.x & 31) << 10) + (threadIdx.x << 2);
    float acc[8] = {0,0,0,0,0,0,0,0};
    #pragma unroll
    for (int i = 0; i < 4; i++) {
        float t[4];
        compute_t(b, l0 + i, P, t);
        #pragma unroll
        for (int k = 0; k < 4; k++) { acc[k] += t[k]; acc[4+k] += t[k]*t[k]; }
    }
    block_reduce_atomic<4>(acc, g_sum2, g_ssq2);
}

// P3: moments of weight*beta (for BN3)
__global__ void __launch_bounds__(256) k_stats3(
        const float* __restrict__ w1, const float* __restrict__ b1,
        const float* __restrict__ w2, const float* __restrict__ b2) {
    __shared__ float P[PA3];
    load_chain(P, 3, w1, b1, w2, b2, 0, 0);
    __syncthreads();
    int b  = blockIdx.x >> 5;
    int l0 = ((blockIdx.x & 31) << 10) + (threadIdx.x << 2);
    float acc[16];
    #pragma unroll
    for (int k = 0; k < 16; k++) acc[k] = 0.f;
    #pragma unroll
    for (int i = 0; i < 4; i++) {
        float wb[8];
        compute_wb(b, l0 + i, P, wb);
        #pragma unroll
        for (int k = 0; k < 8; k++) { acc[k] += wb[k]; acc[8+k] += wb[k]*wb[k]; }
    }
    block_reduce_atomic<8>(acc, g_sum3, g_ssq3);
}

// P4: moments of y = x + conv_out(aggr) (for BN4)
__global__ void __launch_bounds__(256) k_stats4(
        const float* __restrict__ x,
        const float* __restrict__ w1, const float* __restrict__ b1,
        const float* __restrict__ w2, const float* __restrict__ b2,
        const float* __restrict__ wo, const float* __restrict__ bo) {
    __shared__ float P[PA4];
    __shared__ float part[8][64];
    load_chain(P, 4, w1, b1, w2, b2, wo, bo);
    __syncthreads();
    int b  = blockIdx.x >> 5;
    int l0 = ((blockIdx.x & 31) << 10) + (threadIdx.x << 2);
    float ag[4][8];
    #pragma unroll
    for (int i = 0; i < 4; i++) {
        float wb[8];
        compute_wb(b, l0 + i, P, wb);
        #pragma unroll
        for (int o = 0; o < 8; o++) ag[i][o] = fmaxf(fmaf(P[PA3+o], wb[o], P[PC3+o]), 0.f);
    }
    const float* xb = x + (size_t)b * Hh * Ll + l0;
    int lane = threadIdx.x & 31, warp = threadIdx.x >> 5;
    for (int c = 0; c < 32; c++) {
        float4 xv = *reinterpret_cast<const float4*>(xb + (size_t)c * Ll);
        float xa[4] = {xv.x, xv.y, xv.z, xv.w};
        float s = 0.f, q = 0.f;
        #pragma unroll
        for (int i = 0; i < 4; i++) {
            float y = xa[i] + P[PBO+c];
            #pragma unroll
            for (int o = 0; o < 8; o++) y = fmaf(P[PWO+c*8+o], ag[i][o], y);
            s += y; q += y*y;
        }
        #pragma unroll
        for (int o = 16; o; o >>= 1) {
            s += __shfl_down_sync(0xffffffffu, s, o);
            q += __shfl_down_sync(0xffffffffu, q, o);
        }
        if (lane == 0) { part[warp][2*c] = s; part[warp][2*c+1] = q; }
    }
    __syncthreads();
    for (int j = threadIdx.x; j < 64; j += blockDim.x) {
        float s = 0.f;
        #pragma unroll
        for (int w = 0; w < 8; w++) s += part[w][j];
        if ((j & 1) == 0) atomicAdd(&g_sum4[j >> 1], (double)s);
        else              atomicAdd(&g_ssq4[j >> 1], (double)s);
    }
}

// P5: final output
__global__ void __launch_bounds__(256) k_out(
        const float* __restrict__ x,
        const float* __restrict__ w1, const float* __restrict__ b1,
        const float* __restrict__ w2, const float* __restrict__ b2,
        const float* __restrict__ wo, const float* __restrict__ bo,
        float* __restrict__ out) {
    __shared__ float P[PTOT];
    load_chain(P, 5, w1, b1, w2, b2, wo, bo);
    __syncthreads();
    int b  = blockIdx.x >> 5;
    int l0 = ((blockIdx.x & 31) << 10) + (threadIdx.x << 2);
    float ag[4][8];
    #pragma unroll
    for (int i = 0; i < 4; i++) {
        float wb[8];
        compute_wb(b, l0 + i, P, wb);
        #pragma unroll
        for (int o = 0; o < 8; o++) ag[i][o] = fmaxf(fmaf(P[PA3+o], wb[o], P[PC3+o]), 0.f);
    }
    const float* xb = x + (size_t)b * Hh * Ll + l0;
    float* ob = out + (size_t)b * Hh * Ll + l0;
    for (int c = 0; c < 32; c++) {
        float4 xv = *reinterpret_cast<const float4*>(xb + (size_t)c * Ll);
        float xa[4] = {xv.x, xv.y, xv.z, xv.w};
        float oa[4];
        #pragma unroll
        for (int i = 0; i < 4; i++) {
            float y = xa[i] + P[PBO+c];
            #pragma unroll
            for (int o = 0; o < 8; o++) y = fmaf(P[PWO+c*8+o], ag[i][o], y);
            oa[i] = fmaxf(fmaf(P[PA4+c], y, P[PC4+c]), 0.f);
        }
        float4 ov = make_float4(oa[0], oa[1], oa[2], oa[3]);
        *reinterpret_cast<float4*>(ob + (size_t)c * Ll) = ov;
    }
}

// ---------------- host ----------------
extern "C" void kernel_launch(void* const* d_in, const int* in_sizes, int n_in,
                              void* d_out, int out_size) {
    const float* x      = (const float*)d_in[0];
    const float* w_phi  = (const float*)d_in[1];
    const float* b_phi  = (const float*)d_in[2];
    const float* w_psi  = (const float*)d_in[3];
    const float* b_psi  = (const float*)d_in[4];
    const float* w_beta = (const float*)d_in[5];
    const float* b_beta = (const float*)d_in[6];
    const float* w_cw1  = (const float*)d_in[7];
    const float* b_cw1  = (const float*)d_in[8];
    const float* w_cw2  = (const float*)d_in[9];
    const float* b_cw2  = (const float*)d_in[10];
    const float* w_out  = (const float*)d_in[11];
    const float* b_out  = (const float*)d_in[12];
    const float* gcat   = (const float*)d_in[13];
    const float* becat  = (const float*)d_in[14];
    const float* gim    = (const float*)d_in[15];
    const float* beim   = (const float*)d_in[16];
    const float* gag    = (const float*)d_in[17];
    const float* beag   = (const float*)d_in[18];
    const float* ghid   = (const float*)d_in[19];
    const float* behid  = (const float*)d_in[20];
    float* out = (float*)d_out;

    dim3 grid(1024), blk(256);
    k_zero<<<1, 32>>>();
    k_proj<<<grid, blk>>>(x, w_phi, b_phi, w_psi, b_psi, w_beta, b_beta);
    k_fin1<<<1, 256>>>(gcat, becat);
    k_stats2<<<grid, blk>>>(w_cw1, b_cw1);
    k_fin<<<1, 32>>>(2, gim, beim);
    k_stats3<<<grid, blk>>>(w_cw1, b_cw1, w_cw2, b_cw2);
    k_fin<<<1, 32>>>(3, gag, beag);
    k_stats4<<<grid, blk>>>(x, w_cw1, b_cw1, w_cw2, b_cw2, w_out, b_out);
    k_fin<<<1, 32>>>(4, ghid, behid);
    k_out<<<grid, blk>>>(x, w_cw1, b_cw1, w_cw2, b_cw2, w_out, b_out, out);
}

// round 3
// speedup vs baseline: 1.1399x; 1.1399x over previous
#include <cuda_runtime.h>
#include <math.h>

#define Bb 32
#define Hh 32
#define Ll 32768
#define NTOT (Bb*Ll)
#define TILE 1024

// ---------------- scratch ----------------
__device__ float2 g_phi[NTOT];        // 8 MB
__device__ float2 g_psi[NTOT];        // 8 MB
__device__ float4 g_beta[2*NTOT];     // 32 MB

__device__ double g_sum1[4], g_ssq1[4];
__device__ double g_sum2[4], g_ssq2[4];
__device__ double g_sum3[8], g_ssq3[8];
__device__ double g_sum4[32], g_ssq4[32];

__device__ float g_a1[16], g_c1[16];
__device__ float g_a2[4],  g_c2[4];
__device__ float g_a3[8],  g_c3[8];
__device__ float g_a4[32], g_c4[32];

// shared-param layout offsets
#define PA1 0
#define PC1 16
#define PW1 32
#define PB1 96
#define PA2 100
#define PC2 104
#define PW2 108
#define PB2 140
#define PA3 148
#define PC3 156
#define PWO 164
#define PBO 420
#define PA4 452
#define PC4 484
#define PTOT 516

// ---------------- helpers ----------------
template<int NCH>
__device__ __forceinline__ void block_reduce_atomic(const float* acc, double* sums, double* ssqs) {
    __shared__ float red[8][2*NCH];
    int lane = threadIdx.x & 31, warp = threadIdx.x >> 5;
    #pragma unroll
    for (int j = 0; j < 2*NCH; j++) {
        float v = acc[j];
        #pragma unroll
        for (int o = 16; o; o >>= 1) v += __shfl_down_sync(0xffffffffu, v, o);
        if (lane == 0) red[warp][j] = v;
    }
    __syncthreads();
    for (int j = threadIdx.x; j < 2*NCH; j += blockDim.x) {
        float s = 0.f;
        #pragma unroll
        for (int w = 0; w < 8; w++) s += red[w][j];
        if (j < NCH) atomicAdd(&sums[j], (double)s);
        else         atomicAdd(&ssqs[j-NCH], (double)s);
    }
}

__device__ __forceinline__ void load_chain(float* P, int level,
        const float* w1, const float* b1, const float* w2, const float* b2,
        const float* wo, const float* bo) {
    int t = threadIdx.x, bd = blockDim.x;
    for (int i = t; i < 16; i += bd) { P[PA1+i] = g_a1[i]; P[PC1+i] = g_c1[i]; }
    for (int i = t; i < 64; i += bd) P[PW1+i] = w1[i];
    for (int i = t; i < 4;  i += bd) P[PB1+i] = b1[i];
    if (level >= 3) {
        for (int i = t; i < 4;  i += bd) { P[PA2+i] = g_a2[i]; P[PC2+i] = g_c2[i]; }
        for (int i = t; i < 32; i += bd) P[PW2+i] = w2[i];
        for (int i = t; i < 8;  i += bd) P[PB2+i] = b2[i];
    }
    if (level >= 4) {
        for (int i = t; i < 8;   i += bd) { P[PA3+i] = g_a3[i]; P[PC3+i] = g_c3[i]; }
        for (int i = t; i < 256; i += bd) P[PWO+i] = wo[i];
        for (int i = t; i < 32;  i += bd) P[PBO+i] = bo[i];
    }
    if (level >= 5) {
        for (int i = t; i < 32; i += bd) { P[PA4+i] = g_a4[i]; P[PC4+i] = g_c4[i]; }
    }
}

// stage phi tile + psi tile with +-3 halo into smem (channel-split planes)
__device__ __forceinline__ void stage_tiles(int b, int l0,
        float* s_ph0, float* s_ph1, float* s_ps0, float* s_ps1) {
    size_t base = (size_t)b * Ll;
    for (int i = threadIdx.x; i < TILE; i += 256) {
        float2 p = g_phi[base + l0 + i];
        s_ph0[i] = p.x; s_ph1[i] = p.y;
    }
    for (int i = threadIdx.x; i < TILE + 6; i += 256) {
        int l = l0 + i - 3;
        float2 p = (l >= 0 && l < Ll) ? g_psi[base + l] : make_float2(0.f, 0.f);
        s_ps0[i] = p.x; s_ps1[i] = p.y;
    }
}

// t (4 ch) for element li of the tile, reading staged smem
__device__ __forceinline__ void t_from_smem(const float* P,
        const float* s_ph0, const float* s_ph1,
        const float* s_ps0, const float* s_ps1,
        int li, float t[4]) {
    #pragma unroll
    for (int o = 0; o < 4; o++) t[o] = P[PB1+o];
    float v;
    v = fmaxf(fmaf(P[PA1+0], s_ph0[li], P[PC1+0]), 0.f);
    #pragma unroll
    for (int o = 0; o < 4; o++) t[o] = fmaf(P[PW1+o*16+0], v, t[o]);
    v = fmaxf(fmaf(P[PA1+1], s_ph1[li], P[PC1+1]), 0.f);
    #pragma unroll
    for (int o = 0; o < 4; o++) t[o] = fmaf(P[PW1+o*16+1], v, t[o]);
    #pragma unroll
    for (int j = 0; j < 7; j++) {
        v = fmaxf(fmaf(P[PA1+2+j], s_ps0[li+j], P[PC1+2+j]), 0.f);
        #pragma unroll
        for (int o = 0; o < 4; o++) t[o] = fmaf(P[PW1+o*16+2+j], v, t[o]);
    }
    #pragma unroll
    for (int j = 0; j < 7; j++) {
        v = fmaxf(fmaf(P[PA1+9+j], s_ps1[li+j], P[PC1+9+j]), 0.f);
        #pragma unroll
        for (int o = 0; o < 4; o++) t[o] = fmaf(P[PW1+o*16+9+j], v, t[o]);
    }
}

// weight (8 ch, pre-beta) for element li
__device__ __forceinline__ void w8_from_smem(const float* P,
        const float* s_ph0, const float* s_ph1,
        const float* s_ps0, const float* s_ps1,
        int li, float w8[8]) {
    float t[4];
    t_from_smem(P, s_ph0, s_ph1, s_ps0, s_ps1, li, t);
    float u[4];
    #pragma unroll
    for (int i = 0; i < 4; i++) u[i] = fmaxf(fmaf(P[PA2+i], t[i], P[PC2+i]), 0.f);
    #pragma unroll
    for (int o = 0; o < 8; o++) {
        float w = P[PB2+o];
        #pragma unroll
        for (int i = 0; i < 4; i++) w = fmaf(P[PW2+o*4+i], u[i], w);
        w8[o] = w;
    }
}

// ---------------- kernels ----------------
__global__ void k_zero() {
    int t = threadIdx.x;
    if (t < 4)  { g_sum1[t]=0; g_ssq1[t]=0; g_sum2[t]=0; g_ssq2[t]=0; }
    if (t < 8)  { g_sum3[t]=0; g_ssq3[t]=0; }
    if (t < 32) { g_sum4[t]=0; g_ssq4[t]=0; }
}

// P1: x -> phi, psi, beta ; raw moments of phi/psi
__global__ void __launch_bounds__(256, 2) k_proj(
        const float* __restrict__ x,
        const float* __restrict__ w_phi, const float* __restrict__ b_phi,
        const float* __restrict__ w_psi, const float* __restrict__ b_psi,
        const float* __restrict__ w_beta, const float* __restrict__ b_beta) {
    __shared__ float s_wphi[64], s_wpsi[64], s_wbeta[256], s_b[12];
    for (int i = threadIdx.x; i < 64; i += 256) { s_wphi[i] = w_phi[i]; s_wpsi[i] = w_psi[i]; }
    for (int i = threadIdx.x; i < 256; i += 256) s_wbeta[i] = w_beta[i];
    if (threadIdx.x < 2) { s_b[threadIdx.x] = b_phi[threadIdx.x]; s_b[2+threadIdx.x] = b_psi[threadIdx.x]; }
    if (threadIdx.x < 8) s_b[4+threadIdx.x] = b_beta[threadIdx.x];
    __syncthreads();

    int b  = blockIdx.x >> 5;
    int l0 = ((blockIdx.x & 31) << 10) + (threadIdx.x << 2);

    float ph0[4], ph1[4], ps0[4], ps1[4], bt[8][4];
    #pragma unroll
    for (int i = 0; i < 4; i++) {
        ph0[i]=s_b[0]; ph1[i]=s_b[1]; ps0[i]=s_b[2]; ps1[i]=s_b[3];
        #pragma unroll
        for (int o = 0; o < 8; o++) bt[o][i] = s_b[4+o];
    }
    const float* xb = x + (size_t)b * Hh * Ll + l0;
    #pragma unroll 8
    for (int c = 0; c < 32; c++) {
        float4 xv = *reinterpret_cast<const float4*>(xb + (size_t)c * Ll);
        float xa[4] = {xv.x, xv.y, xv.z, xv.w};
        float wp0 = s_wphi[c], wp1 = s_wphi[32+c];
        float wq0 = s_wpsi[c], wq1 = s_wpsi[32+c];
        #pragma unroll
        for (int i = 0; i < 4; i++) {
            ph0[i] = fmaf(wp0, xa[i], ph0[i]); ph1[i] = fmaf(wp1, xa[i], ph1[i]);
            ps0[i] = fmaf(wq0, xa[i], ps0[i]); ps1[i] = fmaf(wq1, xa[i], ps1[i]);
        }
        #pragma unroll
        for (int o = 0; o < 8; o++) {
            float w = s_wbeta[o*32 + c];
            #pragma unroll
            for (int i = 0; i < 4; i++) bt[o][i] = fmaf(w, xa[i], bt[o][i]);
        }
    }
    size_t base = (size_t)b * Ll + l0;
    float acc[8] = {0,0,0,0,0,0,0,0};
    #pragma unroll
    for (int i = 0; i < 4; i++) {
        g_phi[base+i] = make_float2(ph0[i], ph1[i]);
        g_psi[base+i] = make_float2(ps0[i], ps1[i]);
        g_beta[2*(base+i)  ] = make_float4(bt[0][i], bt[1][i], bt[2][i], bt[3][i]);
        g_beta[2*(base+i)+1] = make_float4(bt[4][i], bt[5][i], bt[6][i], bt[7][i]);
        acc[0]+=ph0[i]; acc[4]+=ph0[i]*ph0[i];
        acc[1]+=ph1[i]; acc[5]+=ph1[i]*ph1[i];
        acc[2]+=ps0[i]; acc[6]+=ps0[i]*ps0[i];
        acc[3]+=ps1[i]; acc[7]+=ps1[i]*ps1[i];
    }
    block_reduce_atomic<4>(acc, g_sum1, g_ssq1);
}

// BN1 finalize: shifted-psi channel stats from totals + edge corrections
__global__ void k_fin1(const float* __restrict__ gcat, const float* __restrict__ becat) {
    __shared__ float edge[32][6][2];
    int tid = threadIdx.x;
    if (tid < 192) {
        int b = tid / 6, e = tid % 6;
        int idx = (e < 3) ? e : (Ll - 6 + e);
        float2 p = g_psi[(size_t)b * Ll + idx];
        edge[b][e][0] = p.x; edge[b][e][1] = p.y;
    }
    __syncthreads();
    if (tid < 16) {
        int ch = tid;
        double sum, ssq;
        if (ch < 2) { sum = g_sum1[ch]; ssq = g_ssq1[ch]; }
        else {
            int c = (ch - 2) / 7, j = (ch - 2) % 7, s = j - 3;
            sum = g_sum1[2+c]; ssq = g_ssq1[2+c];
            if (s > 0) {
                for (int b = 0; b < 32; b++)
                    for (int i = 0; i < s; i++) {
                        double v = edge[b][i][c]; sum -= v; ssq -= v*v;
                    }
            } else if (s < 0) {
                for (int b = 0; b < 32; b++)
                    for (int i = 0; i < -s; i++) {
                        double v = edge[b][6+s+i][c]; sum -= v; ssq -= v*v;
                    }
            }
        }
        double mean = sum / (double)NTOT;
        double var  = ssq / (double)NTOT - mean * mean;
        float a = gcat[ch] * (float)(1.0 / sqrt(var + 1e-5));
        g_a1[ch] = a;
        g_c1[ch] = becat[ch] - (float)mean * a;
    }
}

// generic BN finalize for stages 2/3/4
__global__ void k_fin(int which, const float* __restrict__ g, const float* __restrict__ be) {
    const double *sum, *ssq; float *a, *c; int n;
    if (which == 2)      { sum=g_sum2; ssq=g_ssq2; a=g_a2; c=g_c2; n=4; }
    else if (which == 3) { sum=g_sum3; ssq=g_ssq3; a=g_a3; c=g_c3; n=8; }
    else                 { sum=g_sum4; ssq=g_ssq4; a=g_a4; c=g_c4; n=32; }
    int j = threadIdx.x;
    if (j < n) {
        double mean = sum[j] / (double)NTOT;
        double var  = ssq[j] / (double)NTOT - mean * mean;
        float av = g[j] * (float)(1.0 / sqrt(var + 1e-5));
        a[j] = av;
        c[j] = be[j] - (float)mean * av;
    }
}

// P2: moments of t (for BN2), smem-staged
__global__ void __launch_bounds__(256, 4) k_stats2(
        const float* __restrict__ w1, const float* __restrict__ b1) {
    __shared__ float P[PA2];
    __shared__ float s_ph0[TILE], s_ph1[TILE], s_ps0[TILE+6], s_ps1[TILE+6];
    load_chain(P, 2, w1, b1, 0, 0, 0, 0);
    int b  = blockIdx.x >> 5;
    int l0 = (blockIdx.x & 31) << 10;
    stage_tiles(b, l0, s_ph0, s_ph1, s_ps0, s_ps1);
    __syncthreads();
    float acc[8] = {0,0,0,0,0,0,0,0};
    #pragma unroll
    for (int k = 0; k < 4; k++) {
        int li = threadIdx.x + k * 256;
        float t[4];
        t_from_smem(P, s_ph0, s_ph1, s_ps0, s_ps1, li, t);
        #pragma unroll
        for (int j = 0; j < 4; j++) { acc[j] += t[j]; acc[4+j] += t[j]*t[j]; }
    }
    block_reduce_atomic<4>(acc, g_sum2, g_ssq2);
}

// P3: moments of weight*beta (for BN3), smem-staged
__global__ void __launch_bounds__(256, 3) k_stats3(
        const float* __restrict__ w1, const float* __restrict__ b1,
        const float* __restrict__ w2, const float* __restrict__ b2) {
    __shared__ float P[PA3];
    __shared__ float s_ph0[TILE], s_ph1[TILE], s_ps0[TILE+6], s_ps1[TILE+6];
    load_chain(P, 3, w1, b1, w2, b2, 0, 0);
    int b  = blockIdx.x >> 5;
    int l0 = (blockIdx.x & 31) << 10;
    stage_tiles(b, l0, s_ph0, s_ph1, s_ps0, s_ps1);
    __syncthreads();
    size_t base = (size_t)b * Ll + l0;
    float acc[16];
    #pragma unroll
    for (int k = 0; k < 16; k++) acc[k] = 0.f;
    #pragma unroll
    for (int k = 0; k < 4; k++) {
        int li = threadIdx.x + k * 256;
        float w8[8];
        w8_from_smem(P, s_ph0, s_ph1, s_ps0, s_ps1, li, w8);
        float4 b0 = g_beta[2*(base+li)], b1v = g_beta[2*(base+li)+1];
        float wb[8];
        wb[0]=w8[0]*b0.x;  wb[1]=w8[1]*b0.y;  wb[2]=w8[2]*b0.z;  wb[3]=w8[3]*b0.w;
        wb[4]=w8[4]*b1v.x; wb[5]=w8[5]*b1v.y; wb[6]=w8[6]*b1v.z; wb[7]=w8[7]*b1v.w;
        #pragma unroll
        for (int j = 0; j < 8; j++) { acc[j] += wb[j]; acc[8+j] += wb[j]*wb[j]; }
    }
    block_reduce_atomic<8>(acc, g_sum3, g_ssq3);
}

// compute aggr (post-BN3 relu) for this thread's 4 consecutive elements
__device__ __forceinline__ void aggr4(const float* P,
        const float* s_ph0, const float* s_ph1,
        const float* s_ps0, const float* s_ps1,
        size_t base, float ag[4][8]) {
    #pragma unroll
    for (int i = 0; i < 4; i++) {
        int li = (threadIdx.x << 2) + i;
        float w8[8];
        w8_from_smem(P, s_ph0, s_ph1, s_ps0, s_ps1, li, w8);
        float4 b0 = g_beta[2*(base+li)], b1v = g_beta[2*(base+li)+1];
        float wb[8];
        wb[0]=w8[0]*b0.x;  wb[1]=w8[1]*b0.y;  wb[2]=w8[2]*b0.z;  wb[3]=w8[3]*b0.w;
        wb[4]=w8[4]*b1v.x; wb[5]=w8[5]*b1v.y; wb[6]=w8[6]*b1v.z; wb[7]=w8[7]*b1v.w;
        #pragma unroll
        for (int o = 0; o < 8; o++) ag[i][o] = fmaxf(fmaf(P[PA3+o], wb[o], P[PC3+o]), 0.f);
    }
}

// P4: moments of y = x + conv_out(aggr)
__global__ void __launch_bounds__(256, 2) k_stats4(
        const float* __restrict__ x,
        const float* __restrict__ w1, const float* __restrict__ b1,
        const float* __restrict__ w2, const float* __restrict__ b2,
        const float* __restrict__ wo, const float* __restrict__ bo) {
    __shared__ float P[PA4];
    __shared__ float s_ph0[TILE], s_ph1[TILE], s_ps0[TILE+6], s_ps1[TILE+6];
    __shared__ float part[8][64];
    load_chain(P, 4, w1, b1, w2, b2, wo, bo);
    int b  = blockIdx.x >> 5;
    int l0 = (blockIdx.x & 31) << 10;
    stage_tiles(b, l0, s_ph0, s_ph1, s_ps0, s_ps1);
    __syncthreads();
    size_t base = (size_t)b * Ll + l0;
    float ag[4][8];
    aggr4(P, s_ph0, s_ph1, s_ps0, s_ps1, base, ag);

    const float* xb = x + (size_t)b * Hh * Ll + l0 + (threadIdx.x << 2);
    int lane = threadIdx.x & 31, warp = threadIdx.x >> 5;
    #pragma unroll 4
    for (int c = 0; c < 32; c++) {
        float4 xv = *reinterpret_cast<const float4*>(xb + (size_t)c * Ll);
        float xa[4] = {xv.x, xv.y, xv.z, xv.w};
        float s = 0.f, q = 0.f;
        #pragma unroll
        for (int i = 0; i < 4; i++) {
            float y = xa[i] + P[PBO+c];
            #pragma unroll
            for (int o = 0; o < 8; o++) y = fmaf(P[PWO+c*8+o], ag[i][o], y);
            s += y; q += y*y;
        }
        #pragma unroll
        for (int o = 16; o; o >>= 1) {
            s += __shfl_down_sync(0xffffffffu, s, o);
            q += __shfl_down_sync(0xffffffffu, q, o);
        }
        if (lane == 0) { part[warp][2*c] = s; part[warp][2*c+1] = q; }
    }
    __syncthreads();
    for (int j = threadIdx.x; j < 64; j += 256) {
        float s = 0.f;
        #pragma unroll
        for (int w = 0; w < 8; w++) s += part[w][j];
        if ((j & 1) == 0) atomicAdd(&g_sum4[j >> 1], (double)s);
        else              atomicAdd(&g_ssq4[j >> 1], (double)s);
    }
}

// P5: final output
__global__ void __launch_bounds__(256, 2) k_out(
        const float* __restrict__ x,
        const float* __restrict__ w1, const float* __restrict__ b1,
        const float* __restrict__ w2, const float* __restrict__ b2,
        const float* __restrict__ wo, const float* __restrict__ bo,
        float* __restrict__ out) {
    __shared__ float P[PTOT];
    __shared__ float s_ph0[TILE], s_ph1[TILE], s_ps0[TILE+6], s_ps1[TILE+6];
    load_chain(P, 5, w1, b1, w2, b2, wo, bo);
    int b  = blockIdx.x >> 5;
    int l0 = (blockIdx.x & 31) << 10;
    stage_tiles(b, l0, s_ph0, s_ph1, s_ps0, s_ps1);
    __syncthreads();
    size_t base = (size_t)b * Ll + l0;
    float ag[4][8];
    aggr4(P, s_ph0, s_ph1, s_ps0, s_ps1, base, ag);

    const float* xb = x + (size_t)b * Hh * Ll + l0 + (threadIdx.x << 2);
    float* ob = out + (size_t)b * Hh * Ll + l0 + (threadIdx.x << 2);
    #pragma unroll 4
    for (int c = 0; c < 32; c++) {
        float4 xv = *reinterpret_cast<const float4*>(xb + (size_t)c * Ll);
        float xa[4] = {xv.x, xv.y, xv.z, xv.w};
        float oa[4];
        #pragma unroll
        for (int i = 0; i < 4; i++) {
            float y = xa[i] + P[PBO+c];
            #pragma unroll
            for (int o = 0; o < 8; o++) y = fmaf(P[PWO+c*8+o], ag[i][o], y);
            oa[i] = fmaxf(fmaf(P[PA4+c], y, P[PC4+c]), 0.f);
        }
        *reinterpret_cast<float4*>(ob + (size_t)c * Ll) = make_float4(oa[0], oa[1], oa[2], oa[3]);
    }
}

// ---------------- host ----------------
extern "C" void kernel_launch(void* const* d_in, const int* in_sizes, int n_in,
                              void* d_out, int out_size) {
    const float* x      = (const float*)d_in[0];
    const float* w_phi  = (const float*)d_in[1];
    const float* b_phi  = (const float*)d_in[2];
    const float* w_psi  = (const float*)d_in[3];
    const float* b_psi  = (const float*)d_in[4];
    const float* w_beta = (const float*)d_in[5];
    const float* b_beta = (const float*)d_in[6];
    const float* w_cw1  = (const float*)d_in[7];
    const float* b_cw1  = (const float*)d_in[8];
    const float* w_cw2  = (const float*)d_in[9];
    const float* b_cw2  = (const float*)d_in[10];
    const float* w_out  = (const float*)d_in[11];
    const float* b_out  = (const float*)d_in[12];
    const float* gcat   = (const float*)d_in[13];
    const float* becat  = (const float*)d_in[14];
    const float* gim    = (const float*)d_in[15];
    const float* beim   = (const float*)d_in[16];
    const float* gag    = (const float*)d_in[17];
    const float* beag   = (const float*)d_in[18];
    const float* ghid   = (const float*)d_in[19];
    const float* behid  = (const float*)d_in[20];
    float* out = (float*)d_out;

    dim3 grid(1024), blk(256);
    k_zero<<<1, 32>>>();
    k_proj<<<grid, blk>>>(x, w_phi, b_phi, w_psi, b_psi, w_beta, b_beta);
    k_fin1<<<1, 256>>>(gcat, becat);
    k_stats2<<<grid, blk>>>(w_cw1, b_cw1);
    k_fin<<<1, 32>>>(2, gim, beim);
    k_stats3<<<grid, blk>>>(w_cw1, b_cw1, w_cw2, b_cw2);
    k_fin<<<1, 32>>>(3, gag, beag);
    k_stats4<<<grid, blk>>>(x, w_cw1, b_cw1, w_cw2, b_cw2, w_out, b_out);
    k_fin<<<1, 32>>>(4, ghid, behid);
    k_out<<<grid, blk>>>(x, w_cw1, b_cw1, w_cw2, b_cw2, w_out, b_out, out);
}

// round 5
// speedup vs baseline: 1.3974x; 1.2259x over previous
#include <cuda_runtime.h>
#include <math.h>

#define Bb 32
#define Hh 32
#define Ll 32768
#define NTOT (Bb*Ll)

// ---------------- scratch ----------------
__device__ float2 g_phi[NTOT];        // 8 MB
__device__ float2 g_psi[NTOT];        // 8 MB
__device__ float4 g_beta[2*NTOT];     // 32 MB

__device__ double g_sum1[4], g_ssq1[4];
__device__ double g_sum2[4], g_ssq2[4];
__device__ double g_sum3[8], g_ssq3[8];
__device__ double g_sum4[32], g_ssq4[32];

__device__ float g_a1[16], g_c1[16];
__device__ float g_a2[4],  g_c2[4];
__device__ float g_a3[8],  g_c3[8];
__device__ float g_a4[32], g_c4[32];

// ---------------- generic helpers ----------------
template<int NCH>
__device__ __forceinline__ void block_reduce_atomic(const float* acc, double* sums, double* ssqs) {
    __shared__ float red[8][2*NCH];
    int lane = threadIdx.x & 31, warp = threadIdx.x >> 5;
    #pragma unroll
    for (int j = 0; j < 2*NCH; j++) {
        float v = acc[j];
        #pragma unroll
        for (int o = 16; o; o >>= 1) v += __shfl_down_sync(0xffffffffu, v, o);
        if (lane == 0) red[warp][j] = v;
    }
    __syncthreads();
    for (int j = threadIdx.x; j < 2*NCH; j += blockDim.x) {
        float s = 0.f;
        #pragma unroll
        for (int w = 0; w < 8; w++) s += red[w][j];
        if (j < NCH) atomicAdd(&sums[j], (double)s);
        else         atomicAdd(&ssqs[j-NCH], (double)s);
    }
}

// stage phi/psi tiles (halo +-3) into channel-split smem planes
template<int T>
__device__ __forceinline__ void stage_tiles(int b, int l0,
        float* s_ph0, float* s_ph1, float* s_ps0, float* s_ps1) {
    size_t base = (size_t)b * Ll;
    for (int i = threadIdx.x; i < T; i += 256) {
        float2 p = g_phi[base + l0 + i];
        s_ph0[i] = p.x; s_ph1[i] = p.y;
    }
    for (int i = threadIdx.x; i < T + 6; i += 256) {
        int l = l0 + i - 3;
        float2 p = (l >= 0 && l < Ll) ? g_psi[base + l] : make_float2(0.f, 0.f);
        s_ps0[i] = p.x; s_ps1[i] = p.y;
    }
}

// stage packed params for stage-1 (BN1 affine + conv_w1)
__device__ __forceinline__ void stage_params_t(float2* s_ac1, float4* s_w1t, float4* s_b1v,
        const float* __restrict__ w1, const float* __restrict__ b1) {
    int t = threadIdx.x;
    if (t < 16) {
        s_ac1[t] = make_float2(g_a1[t], g_c1[t]);
        s_w1t[t] = make_float4(w1[t], w1[16+t], w1[32+t], w1[48+t]);
    }
    if (t == 16) *s_b1v = make_float4(b1[0], b1[1], b1[2], b1[3]);
}

// stage packed params for stage-2 (BN2 affine + conv_w2)
__device__ __forceinline__ void stage_params_2(float4* s_w2v, float* s_b2,
        float4* s_a2v, float4* s_c2v,
        const float* __restrict__ w2, const float* __restrict__ b2) {
    int t = threadIdx.x;
    if (t >= 32 && t < 40) {
        int o = t - 32;
        s_w2v[o] = make_float4(w2[o*4], w2[o*4+1], w2[o*4+2], w2[o*4+3]);
        s_b2[o]  = b2[o];
    }
    if (t == 40) *s_a2v = make_float4(g_a2[0], g_a2[1], g_a2[2], g_a2[3]);
    if (t == 41) *s_c2v = make_float4(g_c2[0], g_c2[1], g_c2[2], g_c2[3]);
}

// channel-outer t computation for NE elements at li0, li0+STRIDE, ...
template<int NE, int STRIDE>
__device__ __forceinline__ void t_multi(
        const float* s_ph0, const float* s_ph1,
        const float* s_ps0, const float* s_ps1,
        const float2* s_ac1, const float4* s_w1t, float4 b1v,
        int li0, float t[NE][4]) {
    #pragma unroll
    for (int e = 0; e < NE; e++) {
        t[e][0] = b1v.x; t[e][1] = b1v.y; t[e][2] = b1v.z; t[e][3] = b1v.w;
    }
    {
        float2 ac = s_ac1[0]; float4 w = s_w1t[0];
        #pragma unroll
        for (int e = 0; e < NE; e++) {
            float v = fmaxf(fmaf(ac.x, s_ph0[li0 + e*STRIDE], ac.y), 0.f);
            t[e][0] = fmaf(w.x, v, t[e][0]); t[e][1] = fmaf(w.y, v, t[e][1]);
            t[e][2] = fmaf(w.z, v, t[e][2]); t[e][3] = fmaf(w.w, v, t[e][3]);
        }
    }
    {
        float2 ac = s_ac1[1]; float4 w = s_w1t[1];
        #pragma unroll
        for (int e = 0; e < NE; e++) {
            float v = fmaxf(fmaf(ac.x, s_ph1[li0 + e*STRIDE], ac.y), 0.f);
            t[e][0] = fmaf(w.x, v, t[e][0]); t[e][1] = fmaf(w.y, v, t[e][1]);
            t[e][2] = fmaf(w.z, v, t[e][2]); t[e][3] = fmaf(w.w, v, t[e][3]);
        }
    }
    #pragma unroll
    for (int j = 0; j < 7; j++) {
        float2 ac = s_ac1[2+j]; float4 w = s_w1t[2+j];
        #pragma unroll
        for (int e = 0; e < NE; e++) {
            float v = fmaxf(fmaf(ac.x, s_ps0[li0 + e*STRIDE + j], ac.y), 0.f);
            t[e][0] = fmaf(w.x, v, t[e][0]); t[e][1] = fmaf(w.y, v, t[e][1]);
            t[e][2] = fmaf(w.z, v, t[e][2]); t[e][3] = fmaf(w.w, v, t[e][3]);
        }
    }
    #pragma unroll
    for (int j = 0; j < 7; j++) {
        float2 ac = s_ac1[9+j]; float4 w = s_w1t[9+j];
        #pragma unroll
        for (int e = 0; e < NE; e++) {
            float v = fmaxf(fmaf(ac.x, s_ps1[li0 + e*STRIDE + j], ac.y), 0.f);
            t[e][0] = fmaf(w.x, v, t[e][0]); t[e][1] = fmaf(w.y, v, t[e][1]);
            t[e][2] = fmaf(w.z, v, t[e][2]); t[e][3] = fmaf(w.w, v, t[e][3]);
        }
    }
}

// stage-2: t -> w8 (pre-beta conv weight output), NE elements
template<int NE>
__device__ __forceinline__ void w8_multi(const float t[NE][4],
        float4 a2v, float4 c2v, const float4* s_w2v, const float* s_b2,
        float w8[NE][8]) {
    float u[NE][4];
    #pragma unroll
    for (int e = 0; e < NE; e++) {
        u[e][0] = fmaxf(fmaf(a2v.x, t[e][0], c2v.x), 0.f);
        u[e][1] = fmaxf(fmaf(a2v.y, t[e][1], c2v.y), 0.f);
        u[e][2] = fmaxf(fmaf(a2v.z, t[e][2], c2v.z), 0.f);
        u[e][3] = fmaxf(fmaf(a2v.w, t[e][3], c2v.w), 0.f);
    }
    #pragma unroll
    for (int o = 0; o < 8; o++) {
        float4 w = s_w2v[o]; float bb = s_b2[o];
        #pragma unroll
        for (int e = 0; e < NE; e++) {
            float v = fmaf(w.x, u[e][0], bb);
            v = fmaf(w.y, u[e][1], v);
            v = fmaf(w.z, u[e][2], v);
            v = fmaf(w.w, u[e][3], v);
            w8[e][o] = v;
        }
    }
}

// ---------------- kernels ----------------
__global__ void k_zero() {
    int t = threadIdx.x;
    if (t < 4)  { g_sum1[t]=0; g_ssq1[t]=0; g_sum2[t]=0; g_ssq2[t]=0; }
    if (t < 8)  { g_sum3[t]=0; g_ssq3[t]=0; }
    if (t < 32) { g_sum4[t]=0; g_ssq4[t]=0; }
}

// P1: x -> phi, psi, beta ; raw moments of phi/psi
__global__ void __launch_bounds__(256, 3) k_proj(
        const float* __restrict__ x,
        const float* __restrict__ w_phi, const float* __restrict__ b_phi,
        const float* __restrict__ w_psi, const float* __restrict__ b_psi,
        const float* __restrict__ w_beta, const float* __restrict__ b_beta) {
    __shared__ float s_wphi[64], s_wpsi[64], s_wbeta[256], s_b[12];
    for (int i = threadIdx.x; i < 64; i += 256) { s_wphi[i] = w_phi[i]; s_wpsi[i] = w_psi[i]; }
    for (int i = threadIdx.x; i < 256; i += 256) s_wbeta[i] = w_beta[i];
    if (threadIdx.x < 2) { s_b[threadIdx.x] = b_phi[threadIdx.x]; s_b[2+threadIdx.x] = b_psi[threadIdx.x]; }
    if (threadIdx.x < 8) s_b[4+threadIdx.x] = b_beta[threadIdx.x];
    __syncthreads();

    int b  = blockIdx.x >> 5;
    int l0 = ((blockIdx.x & 31) << 10) + (threadIdx.x << 2);

    float ph0[4], ph1[4], ps0[4], ps1[4], bt[8][4];
    #pragma unroll
    for (int i = 0; i < 4; i++) {
        ph0[i]=s_b[0]; ph1[i]=s_b[1]; ps0[i]=s_b[2]; ps1[i]=s_b[3];
        #pragma unroll
        for (int o = 0; o < 8; o++) bt[o][i] = s_b[4+o];
    }
    const float* xb = x + (size_t)b * Hh * Ll + l0;
    #pragma unroll 8
    for (int c = 0; c < 32; c++) {
        float4 xv = *reinterpret_cast<const float4*>(xb + (size_t)c * Ll);
        float xa[4] = {xv.x, xv.y, xv.z, xv.w};
        float wp0 = s_wphi[c], wp1 = s_wphi[32+c];
        float wq0 = s_wpsi[c], wq1 = s_wpsi[32+c];
        #pragma unroll
        for (int i = 0; i < 4; i++) {
            ph0[i] = fmaf(wp0, xa[i], ph0[i]); ph1[i] = fmaf(wp1, xa[i], ph1[i]);
            ps0[i] = fmaf(wq0, xa[i], ps0[i]); ps1[i] = fmaf(wq1, xa[i], ps1[i]);
        }
        #pragma unroll
        for (int o = 0; o < 8; o++) {
            float w = s_wbeta[o*32 + c];
            #pragma unroll
            for (int i = 0; i < 4; i++) bt[o][i] = fmaf(w, xa[i], bt[o][i]);
        }
    }
    size_t base = (size_t)b * Ll + l0;
    float acc[8] = {0,0,0,0,0,0,0,0};
    #pragma unroll
    for (int i = 0; i < 4; i++) {
        g_phi[base+i] = make_float2(ph0[i], ph1[i]);
        g_psi[base+i] = make_float2(ps0[i], ps1[i]);
        g_beta[2*(base+i)  ] = make_float4(bt[0][i], bt[1][i], bt[2][i], bt[3][i]);
        g_beta[2*(base+i)+1] = make_float4(bt[4][i], bt[5][i], bt[6][i], bt[7][i]);
        acc[0]+=ph0[i]; acc[4]+=ph0[i]*ph0[i];
        acc[1]+=ph1[i]; acc[5]+=ph1[i]*ph1[i];
        acc[2]+=ps0[i]; acc[6]+=ps0[i]*ps0[i];
        acc[3]+=ps1[i]; acc[7]+=ps1[i]*ps1[i];
    }
    block_reduce_atomic<4>(acc, g_sum1, g_ssq1);
}

// BN1 finalize: shifted-psi channel stats from totals + edge corrections
__global__ void k_fin1(const float* __restrict__ gcat, const float* __restrict__ becat) {
    __shared__ float edge[32][6][2];
    int tid = threadIdx.x;
    if (tid < 192) {
        int b = tid / 6, e = tid % 6;
        int idx = (e < 3) ? e : (Ll - 6 + e);
        float2 p = g_psi[(size_t)b * Ll + idx];
        edge[b][e][0] = p.x; edge[b][e][1] = p.y;
    }
    __syncthreads();
    if (tid < 16) {
        int ch = tid;
        double sum, ssq;
        if (ch < 2) { sum = g_sum1[ch]; ssq = g_ssq1[ch]; }
        else {
            int c = (ch - 2) / 7, j = (ch - 2) % 7, s = j - 3;
            sum = g_sum1[2+c]; ssq = g_ssq1[2+c];
            if (s > 0) {
                for (int b = 0; b < 32; b++)
                    for (int i = 0; i < s; i++) {
                        double v = edge[b][i][c]; sum -= v; ssq -= v*v;
                    }
            } else if (s < 0) {
                for (int b = 0; b < 32; b++)
                    for (int i = 0; i < -s; i++) {
                        double v = edge[b][6+s+i][c]; sum -= v; ssq -= v*v;
                    }
            }
        }
        double mean = sum / (double)NTOT;
        double var  = ssq / (double)NTOT - mean * mean;
        float a = gcat[ch] * (float)(1.0 / sqrt(var + 1e-5));
        g_a1[ch] = a;
        g_c1[ch] = becat[ch] - (float)mean * a;
    }
}

// generic BN finalize for stages 2/3/4
__global__ void k_fin(int which, const float* __restrict__ g, const float* __restrict__ be) {
    const double *sum, *ssq; float *a, *c; int n;
    if (which == 2)      { sum=g_sum2; ssq=g_ssq2; a=g_a2; c=g_c2; n=4; }
    else if (which == 3) { sum=g_sum3; ssq=g_ssq3; a=g_a3; c=g_c3; n=8; }
    else                 { sum=g_sum4; ssq=g_ssq4; a=g_a4; c=g_c4; n=32; }
    int j = threadIdx.x;
    if (j < n) {
        double mean = sum[j] / (double)NTOT;
        double var  = ssq[j] / (double)NTOT - mean * mean;
        float av = g[j] * (float)(1.0 / sqrt(var + 1e-5));
        a[j] = av;
        c[j] = be[j] - (float)mean * av;
    }
}

// P2: moments of t (for BN2). TILE=512, 2 elems/thread, grid 2048.
__global__ void __launch_bounds__(256, 4) k_stats2(
        const float* __restrict__ w1, const float* __restrict__ b1) {
    __shared__ float2 s_ac1[16];
    __shared__ float4 s_w1t[16];
    __shared__ float4 s_b1v;
    __shared__ float s_ph0[512], s_ph1[512], s_ps0[518], s_ps1[518];
    stage_params_t(s_ac1, s_w1t, &s_b1v, w1, b1);
    int b  = blockIdx.x >> 6;
    int l0 = (blockIdx.x & 63) << 9;
    stage_tiles<512>(b, l0, s_ph0, s_ph1, s_ps0, s_ps1);
    __syncthreads();

    float t[2][4];
    t_multi<2, 256>(s_ph0, s_ph1, s_ps0, s_ps1, s_ac1, s_w1t, s_b1v, threadIdx.x, t);
    float acc[8];
    #pragma unroll
    for (int j = 0; j < 4; j++) {
        acc[j]   = t[0][j] + t[1][j];
        acc[4+j] = t[0][j]*t[0][j] + t[1][j]*t[1][j];
    }
    block_reduce_atomic<4>(acc, g_sum2, g_ssq2);
}

// P3: moments of weight*beta (for BN3). TILE=512, 2 elems/thread, grid 2048.
__global__ void __launch_bounds__(256, 4) k_stats3(
        const float* __restrict__ w1, const float* __restrict__ b1,
        const float* __restrict__ w2, const float* __restrict__ b2) {
    __shared__ float2 s_ac1[16];
    __shared__ float4 s_w1t[16];
    __shared__ float4 s_b1v, s_a2v, s_c2v;
    __shared__ float4 s_w2v[8];
    __shared__ float s_b2[8];
    __shared__ float s_ph0[512], s_ph1[512], s_ps0[518], s_ps1[518];
    stage_params_t(s_ac1, s_w1t, &s_b1v, w1, b1);
    stage_params_2(s_w2v, s_b2, &s_a2v, &s_c2v, w2, b2);
    int b  = blockIdx.x >> 6;
    int l0 = (blockIdx.x & 63) << 9;
    stage_tiles<512>(b, l0, s_ph0, s_ph1, s_ps0, s_ps1);
    __syncthreads();

    float t[2][4];
    t_multi<2, 256>(s_ph0, s_ph1, s_ps0, s_ps1, s_ac1, s_w1t, s_b1v, threadIdx.x, t);
    float w8[2][8];
    w8_multi<2>(t, s_a2v, s_c2v, s_w2v, s_b2, w8);

    size_t base = (size_t)b * Ll + l0;
    float acc[16];
    #pragma unroll
    for (int k = 0; k < 16; k++) acc[k] = 0.f;
    #pragma unroll
    for (int e = 0; e < 2; e++) {
        size_t idx = base + threadIdx.x + e*256;
        float4 b0 = g_beta[2*idx], b1v = g_beta[2*idx+1];
        float wb[8];
        wb[0]=w8[e][0]*b0.x;  wb[1]=w8[e][1]*b0.y;  wb[2]=w8[e][2]*b0.z;  wb[3]=w8[e][3]*b0.w;
        wb[4]=w8[e][4]*b1v.x; wb[5]=w8[e][5]*b1v.y; wb[6]=w8[e][6]*b1v.z; wb[7]=w8[e][7]*b1v.w;
        #pragma unroll
        for (int j = 0; j < 8; j++) { acc[j] += wb[j]; acc[8+j] += wb[j]*wb[j]; }
    }
    block_reduce_atomic<8>(acc, g_sum3, g_ssq3);
}

// aggr (post-BN3 relu) for this thread's 4 consecutive elements
__device__ __forceinline__ void aggr4(
        const float* s_ph0, const float* s_ph1,
        const float* s_ps0, const float* s_ps1,
        const float2* s_ac1, const float4* s_w1t, float4 b1v,
        float4 a2v, float4 c2v, const float4* s_w2v, const float* s_b2,
        const float2* s_ac3,
        size_t base, float ag[4][8]) {
    int li0 = threadIdx.x << 2;
    float t[4][4];
    t_multi<4, 1>(s_ph0, s_ph1, s_ps0, s_ps1, s_ac1, s_w1t, b1v, li0, t);
    float w8[4][8];
    w8_multi<4>(t, a2v, c2v, s_w2v, s_b2, w8);
    #pragma unroll
    for (int i = 0; i < 4; i++) {
        size_t idx = base + li0 + i;
        float4 b0 = g_beta[2*idx], b1q = g_beta[2*idx+1];
        float wb[8];
        wb[0]=w8[i][0]*b0.x;  wb[1]=w8[i][1]*b0.y;  wb[2]=w8[i][2]*b0.z;  wb[3]=w8[i][3]*b0.w;
        wb[4]=w8[i][4]*b1q.x; wb[5]=w8[i][5]*b1q.y; wb[6]=w8[i][6]*b1q.z; wb[7]=w8[i][7]*b1q.w;
        #pragma unroll
        for (int o = 0; o < 8; o++) {
            float2 ac = s_ac3[o];
            ag[i][o] = fmaxf(fmaf(ac.x, wb[o], ac.y), 0.f);
        }
    }
}

__device__ __forceinline__ void stage_params_3(float2* s_ac3) {
    int t = threadIdx.x;
    if (t >= 48 && t < 56) s_ac3[t-48] = make_float2(g_a3[t-48], g_c3[t-48]);
}

// P4: moments of y = x + conv_out(aggr). TILE=1024, grid 1024.
__global__ void __launch_bounds__(256, 2) k_stats4(
        const float* __restrict__ x,
        const float* __restrict__ w1, const float* __restrict__ b1,
        const float* __restrict__ w2, const float* __restrict__ b2,
        const float* __restrict__ wo, const float* __restrict__ bo) {
    __shared__ float2 s_ac1[16];
    __shared__ float4 s_w1t[16];
    __shared__ float4 s_b1v, s_a2v, s_c2v;
    __shared__ float4 s_w2v[8];
    __shared__ float s_b2[8];
    __shared__ float2 s_ac3[8];
    __shared__ float s_wo[256], s_bo[32];
    __shared__ float s_ph0[1024], s_ph1[1024], s_ps0[1030], s_ps1[1030];
    __shared__ float part[8][64];
    stage_params_t(s_ac1, s_w1t, &s_b1v, w1, b1);
    stage_params_2(s_w2v, s_b2, &s_a2v, &s_c2v, w2, b2);
    stage_params_3(s_ac3);
    for (int i = threadIdx.x; i < 256; i += 256) s_wo[i] = wo[i];
    if (threadIdx.x >= 64 && threadIdx.x < 96) s_bo[threadIdx.x-64] = bo[threadIdx.x-64];
    int b  = blockIdx.x >> 5;
    int l0 = (blockIdx.x & 31) << 10;
    stage_tiles<1024>(b, l0, s_ph0, s_ph1, s_ps0, s_ps1);
    __syncthreads();

    size_t base = (size_t)b * Ll + l0;
    float ag[4][8];
    aggr4(s_ph0, s_ph1, s_ps0, s_ps1, s_ac1, s_w1t, s_b1v, s_a2v, s_c2v,
          s_w2v, s_b2, s_ac3, base, ag);

    const float* xb = x + (size_t)b * Hh * Ll + l0 + (threadIdx.x << 2);
    int lane = threadIdx.x & 31, warp = threadIdx.x >> 5;
    #pragma unroll 4
    for (int c = 0; c < 32; c++) {
        float4 xv = *reinterpret_cast<const float4*>(xb + (size_t)c * Ll);
        float xa[4] = {xv.x, xv.y, xv.z, xv.w};
        float bc = s_bo[c];
        float s = 0.f, q = 0.f;
        #pragma unroll
        for (int i = 0; i < 4; i++) {
            float y = xa[i] + bc;
            #pragma unroll
            for (int o = 0; o < 8; o++) y = fmaf(s_wo[c*8+o], ag[i][o], y);
            s += y; q += y*y;
        }
        #pragma unroll
        for (int o = 16; o; o >>= 1) {
            s += __shfl_down_sync(0xffffffffu, s, o);
            q += __shfl_down_sync(0xffffffffu, q, o);
        }
        if (lane == 0) { part[warp][2*c] = s; part[warp][2*c+1] = q; }
    }
    __syncthreads();
    for (int j = threadIdx.x; j < 64; j += 256) {
        float s = 0.f;
        #pragma unroll
        for (int w = 0; w < 8; w++) s += part[w][j];
        if ((j & 1) == 0) atomicAdd(&g_sum4[j >> 1], (double)s);
        else              atomicAdd(&g_ssq4[j >> 1], (double)s);
    }
}

// P5: final output. TILE=1024, grid 1024.
__global__ void __launch_bounds__(256, 2) k_out(
        const float* __restrict__ x,
        const float* __restrict__ w1, const float* __restrict__ b1,
        const float* __restrict__ w2, const float* __restrict__ b2,
        const float* __restrict__ wo, const float* __restrict__ bo,
        float* __restrict__ out) {
    __shared__ float2 s_ac1[16];
    __shared__ float4 s_w1t[16];
    __shared__ float4 s_b1v, s_a2v, s_c2v;
    __shared__ float4 s_w2v[8];
    __shared__ float s_b2[8];
    __shared__ float2 s_ac3[8];
    __shared__ float2 s_ac4[32];
    __shared__ float s_wo[256], s_bo[32];
    __shared__ float s_ph0[1024], s_ph1[1024], s_ps0[1030], s_ps1[1030];
    stage_params_t(s_ac1, s_w1t, &s_b1v, w1, b1);
    stage_params_2(s_w2v, s_b2, &s_a2v, &s_c2v, w2, b2);
    stage_params_3(s_ac3);
    for (int i = threadIdx.x; i < 256; i += 256) s_wo[i] = wo[i];
    if (threadIdx.x >= 64 && threadIdx.x < 96) s_bo[threadIdx.x-64] = bo[threadIdx.x-64];
    if (threadIdx.x >= 96 && threadIdx.x < 128) {
        int c = threadIdx.x - 96;
        s_ac4[c] = make_float2(g_a4[c], g_c4[c]);
    }
    int b  = blockIdx.x >> 5;
    int l0 = (blockIdx.x & 31) << 10;
    stage_tiles<1024>(b, l0, s_ph0, s_ph1, s_ps0, s_ps1);
    __syncthreads();

    size_t base = (size_t)b * Ll + l0;
    float ag[4][8];
    aggr4(s_ph0, s_ph1, s_ps0, s_ps1, s_ac1, s_w1t, s_b1v, s_a2v, s_c2v,
          s_w2v, s_b2, s_ac3, base, ag);

    const float* xb = x + (size_t)b * Hh * Ll + l0 + (threadIdx.x << 2);
    float* ob = out + (size_t)b * Hh * Ll + l0 + (threadIdx.x << 2);
    #pragma unroll 4
    for (int c = 0; c < 32; c++) {
        float4 xv = *reinterpret_cast<const float4*>(xb + (size_t)c * Ll);
        float xa[4] = {xv.x, xv.y, xv.z, xv.w};
        float bc = s_bo[c];
        float2 ac4 = s_ac4[c];
        float oa[4];
        #pragma unroll
        for (int i = 0; i < 4; i++) {
            float y = xa[i] + bc;
            #pragma unroll
            for (int o = 0; o < 8; o++) y = fmaf(s_wo[c*8+o], ag[i][o], y);
            oa[i] = fmaxf(fmaf(ac4.x, y, ac4.y), 0.f);
        }
        *reinterpret_cast<float4*>(ob + (size_t)c * Ll) = make_float4(oa[0], oa[1], oa[2], oa[3]);
    }
}

// ---------------- host ----------------
extern "C" void kernel_launch(void* const* d_in, const int* in_sizes, int n_in,
                              void* d_out, int out_size) {
    const float* x      = (const float*)d_in[0];
    const float* w_phi  = (const float*)d_in[1];
    const float* b_phi  = (const float*)d_in[2];
    const float* w_psi  = (const float*)d_in[3];
    const float* b_psi  = (const float*)d_in[4];
    const float* w_beta = (const float*)d_in[5];
    const float* b_beta = (const float*)d_in[6];
    const float* w_cw1  = (const float*)d_in[7];
    const float* b_cw1  = (const float*)d_in[8];
    const float* w_cw2  = (const float*)d_in[9];
    const float* b_cw2  = (const float*)d_in[10];
    const float* w_out  = (const float*)d_in[11];
    const float* b_out  = (const float*)d_in[12];
    const float* gcat   = (const float*)d_in[13];
    const float* becat  = (const float*)d_in[14];
    const float* gim    = (const float*)d_in[15];
    const float* beim   = (const float*)d_in[16];
    const float* gag    = (const float*)d_in[17];
    const float* beag   = (const float*)d_in[18];
    const float* ghid   = (const float*)d_in[19];
    const float* behid  = (const float*)d_in[20];
    float* out = (float*)d_out;

    k_zero<<<1, 32>>>();
    k_proj<<<1024, 256>>>(x, w_phi, b_phi, w_psi, b_psi, w_beta, b_beta);
    k_fin1<<<1, 256>>>(gcat, becat);
    k_stats2<<<2048, 256>>>(w_cw1, b_cw1);
    k_fin<<<1, 32>>>(2, gim, beim);
    k_stats3<<<2048, 256>>>(w_cw1, b_cw1, w_cw2, b_cw2);
    k_fin<<<1, 32>>>(3, gag, beag);
    k_stats4<<<1024, 256>>>(x, w_cw1, b_cw1, w_cw2, b_cw2, w_out, b_out);
    k_fin<<<1, 32>>>(4, ghid, behid);
    k_out<<<1024, 256>>>(x, w_cw1, b_cw1, w_cw2, b_cw2, w_out, b_out, out);
}

// round 7
// speedup vs baseline: 1.6586x; 1.1869x over previous
#include <cuda_runtime.h>
#include <math.h>

#define Bb 32
#define Hh 32
#define Ll 32768
#define NTOT (Bb*Ll)

// ---------------- scratch ----------------
__device__ float2 g_phi[NTOT];        // 8 MB
__device__ float2 g_psi[NTOT];        // 8 MB
__device__ float4 g_beta[2*NTOT];     // 32 MB ; after k_stats3 holds wb (in-place)

__device__ double g_sum1[4], g_ssq1[4];
__device__ double g_sum2[4], g_ssq2[4];
__device__ double g_sum3[8], g_ssq3[8];
__device__ double g_sum4[32], g_ssq4[32];

__device__ float g_a1[16], g_c1[16];
__device__ float g_a2[4],  g_c2[4];
__device__ float g_a3[8],  g_c3[8];
__device__ float g_a4[32], g_c4[32];

// ---------------- generic helpers ----------------
template<int NCH>
__device__ __forceinline__ void block_reduce_atomic(const float* acc, double* sums, double* ssqs) {
    __shared__ float red[8][2*NCH];
    int lane = threadIdx.x & 31, warp = threadIdx.x >> 5;
    #pragma unroll
    for (int j = 0; j < 2*NCH; j++) {
        float v = acc[j];
        #pragma unroll
        for (int o = 16; o; o >>= 1) v += __shfl_down_sync(0xffffffffu, v, o);
        if (lane == 0) red[warp][j] = v;
    }
    __syncthreads();
    for (int j = threadIdx.x; j < 2*NCH; j += blockDim.x) {
        float s = 0.f;
        #pragma unroll
        for (int w = 0; w < 8; w++) s += red[w][j];
        if (j < NCH) atomicAdd(&sums[j], (double)s);
        else         atomicAdd(&ssqs[j-NCH], (double)s);
    }
}

// stage phi/psi tiles (halo +-3) into channel-split smem planes
template<int T>
__device__ __forceinline__ void stage_tiles(int b, int l0,
        float* s_ph0, float* s_ph1, float* s_ps0, float* s_ps1) {
    size_t base = (size_t)b * Ll;
    for (int i = threadIdx.x; i < T; i += 256) {
        float2 p = g_phi[base + l0 + i];
        s_ph0[i] = p.x; s_ph1[i] = p.y;
    }
    for (int i = threadIdx.x; i < T + 6; i += 256) {
        int l = l0 + i - 3;
        float2 p = (l >= 0 && l < Ll) ? g_psi[base + l] : make_float2(0.f, 0.f);
        s_ps0[i] = p.x; s_ps1[i] = p.y;
    }
}

// stage packed params for stage-1 (BN1 affine + conv_w1)
__device__ __forceinline__ void stage_params_t(float2* s_ac1, float4* s_w1t, float4* s_b1v,
        const float* __restrict__ w1, const float* __restrict__ b1) {
    int t = threadIdx.x;
    if (t < 16) {
        s_ac1[t] = make_float2(g_a1[t], g_c1[t]);
        s_w1t[t] = make_float4(w1[t], w1[16+t], w1[32+t], w1[48+t]);
    }
    if (t == 16) *s_b1v = make_float4(b1[0], b1[1], b1[2], b1[3]);
}

// stage packed params for stage-2 (BN2 affine + conv_w2)
__device__ __forceinline__ void stage_params_2(float4* s_w2v, float* s_b2,
        float4* s_a2v, float4* s_c2v,
        const float* __restrict__ w2, const float* __restrict__ b2) {
    int t = threadIdx.x;
    if (t >= 32 && t < 40) {
        int o = t - 32;
        s_w2v[o] = make_float4(w2[o*4], w2[o*4+1], w2[o*4+2], w2[o*4+3]);
        s_b2[o]  = b2[o];
    }
    if (t == 40) *s_a2v = make_float4(g_a2[0], g_a2[1], g_a2[2], g_a2[3]);
    if (t == 41) *s_c2v = make_float4(g_c2[0], g_c2[1], g_c2[2], g_c2[3]);
}

// load 4-element windows from smem planes into registers (LDS.128)
__device__ __forceinline__ void load_windows(
        const float* s_ph0, const float* s_ph1,
        const float* s_ps0, const float* s_ps1, int li0,
        float ph0[4], float ph1[4], float ps0[12], float ps1[12]) {
    *reinterpret_cast<float4*>(ph0) = *reinterpret_cast<const float4*>(s_ph0 + li0);
    *reinterpret_cast<float4*>(ph1) = *reinterpret_cast<const float4*>(s_ph1 + li0);
    #pragma unroll
    for (int k = 0; k < 3; k++) {
        *reinterpret_cast<float4*>(ps0 + 4*k) = *reinterpret_cast<const float4*>(s_ps0 + li0 + 4*k);
        *reinterpret_cast<float4*>(ps1 + 4*k) = *reinterpret_cast<const float4*>(s_ps1 + li0 + 4*k);
    }
}

// t for 4 consecutive elements from register windows
__device__ __forceinline__ void t4_compute(
        const float ph0[4], const float ph1[4],
        const float ps0[12], const float ps1[12],
        const float2* s_ac1, const float4* s_w1t, float4 b1v,
        float t[4][4]) {
    #pragma unroll
    for (int e = 0; e < 4; e++) {
        t[e][0] = b1v.x; t[e][1] = b1v.y; t[e][2] = b1v.z; t[e][3] = b1v.w;
    }
    {
        float2 ac = s_ac1[0]; float4 w = s_w1t[0];
        #pragma unroll
        for (int e = 0; e < 4; e++) {
            float v = fmaxf(fmaf(ac.x, ph0[e], ac.y), 0.f);
            t[e][0] = fmaf(w.x, v, t[e][0]); t[e][1] = fmaf(w.y, v, t[e][1]);
            t[e][2] = fmaf(w.z, v, t[e][2]); t[e][3] = fmaf(w.w, v, t[e][3]);
        }
    }
    {
        float2 ac = s_ac1[1]; float4 w = s_w1t[1];
        #pragma unroll
        for (int e = 0; e < 4; e++) {
            float v = fmaxf(fmaf(ac.x, ph1[e], ac.y), 0.f);
            t[e][0] = fmaf(w.x, v, t[e][0]); t[e][1] = fmaf(w.y, v, t[e][1]);
            t[e][2] = fmaf(w.z, v, t[e][2]); t[e][3] = fmaf(w.w, v, t[e][3]);
        }
    }
    #pragma unroll
    for (int j = 0; j < 7; j++) {
        float2 ac = s_ac1[2+j]; float4 w = s_w1t[2+j];
        #pragma unroll
        for (int e = 0; e < 4; e++) {
            float v = fmaxf(fmaf(ac.x, ps0[e+j], ac.y), 0.f);
            t[e][0] = fmaf(w.x, v, t[e][0]); t[e][1] = fmaf(w.y, v, t[e][1]);
            t[e][2] = fmaf(w.z, v, t[e][2]); t[e][3] = fmaf(w.w, v, t[e][3]);
        }
    }
    #pragma unroll
    for (int j = 0; j < 7; j++) {
        float2 ac = s_ac1[9+j]; float4 w = s_w1t[9+j];
        #pragma unroll
        for (int e = 0; e < 4; e++) {
            float v = fmaxf(fmaf(ac.x, ps1[e+j], ac.y), 0.f);
            t[e][0] = fmaf(w.x, v, t[e][0]); t[e][1] = fmaf(w.y, v, t[e][1]);
            t[e][2] = fmaf(w.z, v, t[e][2]); t[e][3] = fmaf(w.w, v, t[e][3]);
        }
    }
}

// stage-2: t -> w8 (pre-beta conv weight output), 4 elements
__device__ __forceinline__ void w8_compute(const float t[4][4],
        float4 a2v, float4 c2v, const float4* s_w2v, const float* s_b2,
        float w8[4][8]) {
    float u[4][4];
    #pragma unroll
    for (int e = 0; e < 4; e++) {
        u[e][0] = fmaxf(fmaf(a2v.x, t[e][0], c2v.x), 0.f);
        u[e][1] = fmaxf(fmaf(a2v.y, t[e][1], c2v.y), 0.f);
        u[e][2] = fmaxf(fmaf(a2v.z, t[e][2], c2v.z), 0.f);
        u[e][3] = fmaxf(fmaf(a2v.w, t[e][3], c2v.w), 0.f);
    }
    #pragma unroll
    for (int o = 0; o < 8; o++) {
        float4 w = s_w2v[o]; float bb = s_b2[o];
        #pragma unroll
        for (int e = 0; e < 4; e++) {
            float v = fmaf(w.x, u[e][0], bb);
            v = fmaf(w.y, u[e][1], v);
            v = fmaf(w.z, u[e][2], v);
            v = fmaf(w.w, u[e][3], v);
            w8[e][o] = v;
        }
    }
}

// ---------------- kernels ----------------
__global__ void k_zero() {
    int t = threadIdx.x;
    if (t < 4)  { g_sum1[t]=0; g_ssq1[t]=0; g_sum2[t]=0; g_ssq2[t]=0; }
    if (t < 8)  { g_sum3[t]=0; g_ssq3[t]=0; }
    if (t < 32) { g_sum4[t]=0; g_ssq4[t]=0; }
}

// P1: x -> phi, psi, beta ; raw moments of phi/psi
__global__ void __launch_bounds__(256, 3) k_proj(
        const float* __restrict__ x,
        const float* __restrict__ w_phi, const float* __restrict__ b_phi,
        const float* __restrict__ w_psi, const float* __restrict__ b_psi,
        const float* __restrict__ w_beta, const float* __restrict__ b_beta) {
    __shared__ float s_wphi[64], s_wpsi[64], s_wbeta[256], s_b[12];
    for (int i = threadIdx.x; i < 64; i += 256) { s_wphi[i] = w_phi[i]; s_wpsi[i] = w_psi[i]; }
    for (int i = threadIdx.x; i < 256; i += 256) s_wbeta[i] = w_beta[i];
    if (threadIdx.x < 2) { s_b[threadIdx.x] = b_phi[threadIdx.x]; s_b[2+threadIdx.x] = b_psi[threadIdx.x]; }
    if (threadIdx.x < 8) s_b[4+threadIdx.x] = b_beta[threadIdx.x];
    __syncthreads();

    int b  = blockIdx.x >> 5;
    int l0 = ((blockIdx.x & 31) << 10) + (threadIdx.x << 2);

    float ph0[4], ph1[4], ps0[4], ps1[4], bt[8][4];
    #pragma unroll
    for (int i = 0; i < 4; i++) {
        ph0[i]=s_b[0]; ph1[i]=s_b[1]; ps0[i]=s_b[2]; ps1[i]=s_b[3];
        #pragma unroll
        for (int o = 0; o < 8; o++) bt[o][i] = s_b[4+o];
    }
    const float* xb = x + (size_t)b * Hh * Ll + l0;
    #pragma unroll 8
    for (int c = 0; c < 32; c++) {
        float4 xv = *reinterpret_cast<const float4*>(xb + (size_t)c * Ll);
        float xa[4] = {xv.x, xv.y, xv.z, xv.w};
        float wp0 = s_wphi[c], wp1 = s_wphi[32+c];
        float wq0 = s_wpsi[c], wq1 = s_wpsi[32+c];
        #pragma unroll
        for (int i = 0; i < 4; i++) {
            ph0[i] = fmaf(wp0, xa[i], ph0[i]); ph1[i] = fmaf(wp1, xa[i], ph1[i]);
            ps0[i] = fmaf(wq0, xa[i], ps0[i]); ps1[i] = fmaf(wq1, xa[i], ps1[i]);
        }
        #pragma unroll
        for (int o = 0; o < 8; o++) {
            float w = s_wbeta[o*32 + c];
            #pragma unroll
            for (int i = 0; i < 4; i++) bt[o][i] = fmaf(w, xa[i], bt[o][i]);
        }
    }
    size_t base = (size_t)b * Ll + l0;
    float acc[8] = {0,0,0,0,0,0,0,0};
    #pragma unroll
    for (int i = 0; i < 4; i++) {
        g_phi[base+i] = make_float2(ph0[i], ph1[i]);
        g_psi[base+i] = make_float2(ps0[i], ps1[i]);
        g_beta[2*(base+i)  ] = make_float4(bt[0][i], bt[1][i], bt[2][i], bt[3][i]);
        g_beta[2*(base+i)+1] = make_float4(bt[4][i], bt[5][i], bt[6][i], bt[7][i]);
        acc[0]+=ph0[i]; acc[4]+=ph0[i]*ph0[i];
        acc[1]+=ph1[i]; acc[5]+=ph1[i]*ph1[i];
        acc[2]+=ps0[i]; acc[6]+=ps0[i]*ps0[i];
        acc[3]+=ps1[i]; acc[7]+=ps1[i]*ps1[i];
    }
    block_reduce_atomic<4>(acc, g_sum1, g_ssq1);
}

// BN1 finalize: shifted-psi channel stats from totals + edge corrections
__global__ void k_fin1(const float* __restrict__ gcat, const float* __restrict__ becat) {
    __shared__ float edge[32][6][2];
    int tid = threadIdx.x;
    if (tid < 192) {
        int b = tid / 6, e = tid % 6;
        int idx = (e < 3) ? e : (Ll - 6 + e);
        float2 p = g_psi[(size_t)b * Ll + idx];
        edge[b][e][0] = p.x; edge[b][e][1] = p.y;
    }
    __syncthreads();
    if (tid < 16) {
        int ch = tid;
        double sum, ssq;
        if (ch < 2) { sum = g_sum1[ch]; ssq = g_ssq1[ch]; }
        else {
            int c = (ch - 2) / 7, j = (ch - 2) % 7, s = j - 3;
            sum = g_sum1[2+c]; ssq = g_ssq1[2+c];
            if (s > 0) {
                for (int b = 0; b < 32; b++)
                    for (int i = 0; i < s; i++) {
                        double v = edge[b][i][c]; sum -= v; ssq -= v*v;
                    }
            } else if (s < 0) {
                for (int b = 0; b < 32; b++)
                    for (int i = 0; i < -s; i++) {
                        double v = edge[b][6+s+i][c]; sum -= v; ssq -= v*v;
                    }
            }
        }
        double mean = sum / (double)NTOT;
        double var  = ssq / (double)NTOT - mean * mean;
        float a = gcat[ch] * (float)(1.0 / sqrt(var + 1e-5));
        g_a1[ch] = a;
        g_c1[ch] = becat[ch] - (float)mean * a;
    }
}

// generic BN finalize for stages 2/3/4
__global__ void k_fin(int which, const float* __restrict__ g, const float* __restrict__ be) {
    const double *sum, *ssq; float *a, *c; int n;
    if (which == 2)      { sum=g_sum2; ssq=g_ssq2; a=g_a2; c=g_c2; n=4; }
    else if (which == 3) { sum=g_sum3; ssq=g_ssq3; a=g_a3; c=g_c3; n=8; }
    else                 { sum=g_sum4; ssq=g_ssq4; a=g_a4; c=g_c4; n=32; }
    int j = threadIdx.x;
    if (j < n) {
        double mean = sum[j] / (double)NTOT;
        double var  = ssq[j] / (double)NTOT - mean * mean;
        float av = g[j] * (float)(1.0 / sqrt(var + 1e-5));
        a[j] = av;
        c[j] = be[j] - (float)mean * av;
    }
}

// P2: moments of t (for BN2). TILE=1024, 4 consecutive elems/thread, grid 1024.
__global__ void __launch_bounds__(256, 4) k_stats2(
        const float* __restrict__ w1, const float* __restrict__ b1) {
    __shared__ float2 s_ac1[16];
    __shared__ float4 s_w1t[16];
    __shared__ float4 s_b1v;
    __shared__ __align__(16) float s_ph0[1024], s_ph1[1024], s_ps0[1040], s_ps1[1040];
    stage_params_t(s_ac1, s_w1t, &s_b1v, w1, b1);
    int b  = blockIdx.x >> 5;
    int l0 = (blockIdx.x & 31) << 10;
    stage_tiles<1024>(b, l0, s_ph0, s_ph1, s_ps0, s_ps1);
    __syncthreads();

    int li0 = threadIdx.x << 2;
    float ph0[4], ph1[4], ps0[12], ps1[12];
    load_windows(s_ph0, s_ph1, s_ps0, s_ps1, li0, ph0, ph1, ps0, ps1);
    float t[4][4];
    t4_compute(ph0, ph1, ps0, ps1, s_ac1, s_w1t, s_b1v, t);

    float acc[8];
    #pragma unroll
    for (int j = 0; j < 4; j++) {
        acc[j]   = t[0][j] + t[1][j] + t[2][j] + t[3][j];
        acc[4+j] = t[0][j]*t[0][j] + t[1][j]*t[1][j] + t[2][j]*t[2][j] + t[3][j]*t[3][j];
    }
    block_reduce_atomic<4>(acc, g_sum2, g_ssq2);
}

// P3: moments of weight*beta (BN3) AND materialize wb in-place into g_beta.
__global__ void __launch_bounds__(256, 3) k_stats3(
        const float* __restrict__ w1, const float* __restrict__ b1,
        const float* __restrict__ w2, const float* __restrict__ b2) {
    __shared__ float2 s_ac1[16];
    __shared__ float4 s_w1t[16];
    __shared__ float4 s_b1v, s_a2v, s_c2v;
    __shared__ float4 s_w2v[8];
    __shared__ float s_b2[8];
    __shared__ __align__(16) float s_ph0[1024], s_ph1[1024], s_ps0[1040], s_ps1[1040];
    stage_params_t(s_ac1, s_w1t, &s_b1v, w1, b1);
    stage_params_2(s_w2v, s_b2, &s_a2v, &s_c2v, w2, b2);
    int b  = blockIdx.x >> 5;
    int l0 = (blockIdx.x & 31) << 10;
    stage_tiles<1024>(b, l0, s_ph0, s_ph1, s_ps0, s_ps1);
    __syncthreads();

    int li0 = threadIdx.x << 2;
    float ph0[4], ph1[4], ps0[12], ps1[12];
    load_windows(s_ph0, s_ph1, s_ps0, s_ps1, li0, ph0, ph1, ps0, ps1);
    float t[4][4];
    t4_compute(ph0, ph1, ps0, ps1, s_ac1, s_w1t, s_b1v, t);
    float w8[4][8];
    w8_compute(t, s_a2v, s_c2v, s_w2v, s_b2, w8);

    size_t base = (size_t)b * Ll + l0;
    float acc[16];
    #pragma unroll
    for (int k = 0; k < 16; k++) acc[k] = 0.f;
    #pragma unroll
    for (int e = 0; e < 4; e++) {
        size_t idx = base + li0 + e;
        float4 b0 = g_beta[2*idx], b1v = g_beta[2*idx+1];
        float wb[8];
        wb[0]=w8[e][0]*b0.x;  wb[1]=w8[e][1]*b0.y;  wb[2]=w8[e][2]*b0.z;  wb[3]=w8[e][3]*b0.w;
        wb[4]=w8[e][4]*b1v.x; wb[5]=w8[e][5]*b1v.y; wb[6]=w8[e][6]*b1v.z; wb[7]=w8[e][7]*b1v.w;
        g_beta[2*idx]   = make_float4(wb[0], wb[1], wb[2], wb[3]);
        g_beta[2*idx+1] = make_float4(wb[4], wb[5], wb[6], wb[7]);
        #pragma unroll
        for (int j = 0; j < 8; j++) { acc[j] += wb[j]; acc[8+j] += wb[j]*wb[j]; }
    }
    block_reduce_atomic<8>(acc, g_sum3, g_ssq3);
}

// load wb (stored in g_beta) and apply BN3 affine+relu -> ag[4][8]
__device__ __forceinline__ void load_aggr(const float2* s_ac3, size_t base, int li0,
        float ag[4][8]) {
    #pragma unroll
    for (int i = 0; i < 4; i++) {
        size_t idx = base + li0 + i;
        float4 w0 = g_beta[2*idx], w1 = g_beta[2*idx+1];
        float wb[8] = {w0.x, w0.y, w0.z, w0.w, w1.x, w1.y, w1.z, w1.w};
        #pragma unroll
        for (int o = 0; o < 8; o++) {
            float2 ac = s_ac3[o];
            ag[i][o] = fmaxf(fmaf(ac.x, wb[o], ac.y), 0.f);
        }
    }
}

__device__ __forceinline__ void stage_params_3(float2* s_ac3) {
    int t = threadIdx.x;
    if (t >= 48 && t < 56) s_ac3[t-48] = make_float2(g_a3[t-48], g_c3[t-48]);
}

// P4: moments of y = x + conv_out(aggr). Pure streaming: wb + x.
__global__ void __launch_bounds__(256, 3) k_stats4(
        const float* __restrict__ x,
        const float* __restrict__ wo, const float* __restrict__ bo) {
    __shared__ float2 s_ac3[8];
    __shared__ float s_wo[256], s_bo[32];
    __shared__ float part[8][64];
    stage_params_3(s_ac3);
    for (int i = threadIdx.x; i < 256; i += 256) s_wo[i] = wo[i];
    if (threadIdx.x >= 64 && threadIdx.x < 96) s_bo[threadIdx.x-64] = bo[threadIdx.x-64];
    int b  = blockIdx.x >> 5;
    int l0 = (blockIdx.x & 31) << 10;
    __syncthreads();

    size_t base = (size_t)b * Ll + l0;
    int li0 = threadIdx.x << 2;
    float ag[4][8];
    load_aggr(s_ac3, base, li0, ag);

    const float* xb = x + (size_t)b * Hh * Ll + l0 + li0;
    int lane = threadIdx.x & 31, warp = threadIdx.x >> 5;
    #pragma unroll 4
    for (int c = 0; c < 32; c++) {
        float4 xv = *reinterpret_cast<const float4*>(xb + (size_t)c * Ll);
        float xa[4] = {xv.x, xv.y, xv.z, xv.w};
        float bc = s_bo[c];
        float s = 0.f, q = 0.f;
        #pragma unroll
        for (int i = 0; i < 4; i++) {
            float y = xa[i] + bc;
            #pragma unroll
            for (int o = 0; o < 8; o++) y = fmaf(s_wo[c*8+o], ag[i][o], y);
            s += y; q += y*y;
        }
        #pragma unroll
        for (int o = 16; o; o >>= 1) {
            s += __shfl_down_sync(0xffffffffu, s, o);
            q += __shfl_down_sync(0xffffffffu, q, o);
        }
        if (lane == 0) { part[warp][2*c] = s; part[warp][2*c+1] = q; }
    }
    __syncthreads();
    for (int j = threadIdx.x; j < 64; j += 256) {
        float s = 0.f;
        #pragma unroll
        for (int w = 0; w < 8; w++) s += part[w][j];
        if ((j & 1) == 0) atomicAdd(&g_sum4[j >> 1], (double)s);
        else              atomicAdd(&g_ssq4[j >> 1], (double)s);
    }
}

// P5: final output. Pure streaming: wb + x -> out.
__global__ void __launch_bounds__(256, 3) k_out(
        const float* __restrict__ x,
        const float* __restrict__ wo, const float* __restrict__ bo,
        float* __restrict__ out) {
    __shared__ float2 s_ac3[8];
    __shared__ float2 s_ac4[32];
    __shared__ float s_wo[256], s_bo[32];
    stage_params_3(s_ac3);
    for (int i = threadIdx.x; i < 256; i += 256) s_wo[i] = wo[i];
    if (threadIdx.x >= 64 && threadIdx.x < 96) s_bo[threadIdx.x-64] = bo[threadIdx.x-64];
    if (threadIdx.x >= 96 && threadIdx.x < 128) {
        int c = threadIdx.x - 96;
        s_ac4[c] = make_float2(g_a4[c], g_c4[c]);
    }
    int b  = blockIdx.x >> 5;
    int l0 = (blockIdx.x & 31) << 10;
    __syncthreads();

    size_t base = (size_t)b * Ll + l0;
    int li0 = threadIdx.x << 2;
    float ag[4][8];
    load_aggr(s_ac3, base, li0, ag);

    const float* xb = x + (size_t)b * Hh * Ll + l0 + li0;
    float* ob = out + (size_t)b * Hh * Ll + l0 + li0;
    #pragma unroll 4
    for (int c = 0; c < 32; c++) {
        float4 xv = *reinterpret_cast<const float4*>(xb + (size_t)c * Ll);
        float xa[4] = {xv.x, xv.y, xv.z, xv.w};
        float bc = s_bo[c];
        float2 ac4 = s_ac4[c];
        float oa[4];
        #pragma unroll
        for (int i = 0; i < 4; i++) {
            float y = xa[i] + bc;
            #pragma unroll
            for (int o = 0; o < 8; o++) y = fmaf(s_wo[c*8+o], ag[i][o], y);
            oa[i] = fmaxf(fmaf(ac4.x, y, ac4.y), 0.f);
        }
        *reinterpret_cast<float4*>(ob + (size_t)c * Ll) = make_float4(oa[0], oa[1], oa[2], oa[3]);
    }
}

// ---------------- host ----------------
extern "C" void kernel_launch(void* const* d_in, const int* in_sizes, int n_in,
                              void* d_out, int out_size) {
    const float* x      = (const float*)d_in[0];
    const float* w_phi  = (const float*)d_in[1];
    const float* b_phi  = (const float*)d_in[2];
    const float* w_psi  = (const float*)d_in[3];
    const float* b_psi  = (const float*)d_in[4];
    const float* w_beta = (const float*)d_in[5];
    const float* b_beta = (const float*)d_in[6];
    const float* w_cw1  = (const float*)d_in[7];
    const float* b_cw1  = (const float*)d_in[8];
    const float* w_cw2  = (const float*)d_in[9];
    const float* b_cw2  = (const float*)d_in[10];
    const float* w_out  = (const float*)d_in[11];
    const float* b_out  = (const float*)d_in[12];
    const float* gcat   = (const float*)d_in[13];
    const float* becat  = (const float*)d_in[14];
    const float* gim    = (const float*)d_in[15];
    const float* beim   = (const float*)d_in[16];
    const float* gag    = (const float*)d_in[17];
    const float* beag   = (const float*)d_in[18];
    const float* ghid   = (const float*)d_in[19];
    const float* behid  = (const float*)d_in[20];
    float* out = (float*)d_out;

    k_zero<<<1, 32>>>();
    k_proj<<<1024, 256>>>(x, w_phi, b_phi, w_psi, b_psi, w_beta, b_beta);
    k_fin1<<<1, 256>>>(gcat, becat);
    k_stats2<<<1024, 256>>>(w_cw1, b_cw1);
    k_fin<<<1, 32>>>(2, gim, beim);
    k_stats3<<<1024, 256>>>(w_cw1, b_cw1, w_cw2, b_cw2);
    k_fin<<<1, 32>>>(3, gag, beag);
    k_stats4<<<1024, 256>>>(x, w_out, b_out);
    k_fin<<<1, 32>>>(4, ghid, behid);
    k_out<<<1024, 256>>>(x, w_out, b_out, out);
}